// round 5
// baseline (speedup 1.0000x reference)
#include <cuda_runtime.h>
#include <cuda_bf16.h>
#include <cstdint>

#define D     128
#define NSEG  4096
#define BM    128
#define NTHR  256
#define CH    512
#define RSEG  32

#define WS    136            // padded bf16 row stride (272B, 16B multiple)
#define WS2   (WS * 2)
#define TILEB (BM * WS2)     // 34816 bytes per bf16 tile

// smem byte offsets
#define OXH  0
#define OXL  (TILEB)
#define OW1H (2 * TILEB)
#define OW1L (3 * TILEB)
#define OW2H (4 * TILEB)
#define OW2L (5 * TILEB)
#define OB1  (6 * TILEB)
#define OB2  (6 * TILEB + 512)
#define OIDX (6 * TILEB + 1024)
#define SMEM_PHI (6 * TILEB + 1536)

// ---------------- scratch ----------------------------------------------------
__device__ float g_xsum[NSEG * D];
__device__ float g_rho [NSEG * D];

// ---------------- helpers ----------------------------------------------------
__device__ __forceinline__ uint32_t smem_u32(const void* p) {
    uint32_t a;
    asm("{ .reg .u64 t; cvta.to.shared.u64 t, %1; cvt.u32.u64 %0, t; }"
        : "=r"(a) : "l"(p));
    return a;
}
__device__ __forceinline__ void ldsm_x4(uint32_t r[4], uint32_t addr) {
    asm volatile("ldmatrix.sync.aligned.m8n8.x4.shared.b16 {%0,%1,%2,%3}, [%4];"
                 : "=r"(r[0]), "=r"(r[1]), "=r"(r[2]), "=r"(r[3]) : "r"(addr));
}
__device__ __forceinline__ void mma_bf16(float c[4], const uint32_t a[4],
                                         const uint32_t* b) {
    asm volatile("mma.sync.aligned.m16n8k16.row.col.f32.bf16.bf16.f32 "
                 "{%0,%1,%2,%3}, {%4,%5,%6,%7}, {%8,%9}, {%0,%1,%2,%3};"
                 : "+f"(c[0]), "+f"(c[1]), "+f"(c[2]), "+f"(c[3])
                 : "r"(a[0]), "r"(a[1]), "r"(a[2]), "r"(a[3]),
                   "r"(b[0]), "r"(b[1]));
}
__device__ __forceinline__ void bsplit(float v, uint32_t& h, uint32_t& l) {
    __nv_bfloat16 bh = __float2bfloat16(v);
    h = (uint32_t)__bfloat16_as_ushort(bh);
    float r = v - __bfloat162float(bh);
    l = (uint32_t)__bfloat16_as_ushort(__float2bfloat16(r));
}

// ---------------- k0: zero ---------------------------------------------------
__global__ void k_zero() {
    int i = blockIdx.x * blockDim.x + threadIdx.x;
    if (i < NSEG * D / 4)
        reinterpret_cast<float4*>(g_xsum)[i] = make_float4(0.f, 0.f, 0.f, 0.f);
}

// ---------------- k1: segment sum (idx sorted) --------------------------------
__global__ void k_segsum(const float* __restrict__ x,
                         const int*   __restrict__ idx, int n) {
    int f = threadIdx.x;
    long start = (long)blockIdx.x * CH;
    if (start >= n) return;
    long end = start + CH; if (end > n) end = n;

    int   cur = __ldg(&idx[start]);
    float acc = 0.f;
    long nn = start;
    for (; nn + 8 <= end; nn += 8) {
        float v[8]; int s[8];
        #pragma unroll
        for (int u = 0; u < 8; u++) {
            s[u] = __ldg(&idx[nn + u]);
            v[u] = __ldg(&x[(nn + u) * D + f]);
        }
        #pragma unroll
        for (int u = 0; u < 8; u++) {
            if (s[u] != cur) {
                atomicAdd(&g_xsum[(long)cur * D + f], acc);
                acc = 0.f; cur = s[u];
            }
            acc += v[u];
        }
    }
    for (; nn < end; ++nn) {
        int s = __ldg(&idx[nn]);
        float v = __ldg(&x[nn * D + f]);
        if (s != cur) {
            atomicAdd(&g_xsum[(long)cur * D + f], acc);
            acc = 0.f; cur = s;
        }
        acc += v;
    }
    atomicAdd(&g_xsum[(long)cur * D + f], acc);
}

// ---------------- k2: rho MLP on segment sums ----------------------------------
__global__ void k_rho(const float* __restrict__ w1, const float* __restrict__ b1,
                      const float* __restrict__ w2, const float* __restrict__ b2) {
    extern __shared__ float sm[];
    float* sW = sm;
    float* sX = sW + D * D;
    float* sH = sX + RSEG * D;
    float* sB = sH + RSEG * D;
    int j = threadIdx.x;
    int seg0 = blockIdx.x * RSEG;

    for (int r = 0; r < RSEG; r++)
        sX[r * D + j] = g_xsum[(seg0 + r) * D + j];
    for (int i = j; i < D * D; i += blockDim.x) sW[i] = w1[i];
    sB[j] = b1[j];
    __syncthreads();

    for (int r = 0; r < RSEG; r++) {
        float acc = sB[j];
        #pragma unroll 8
        for (int k = 0; k < D; k++) acc += sX[r * D + k] * sW[k * D + j];
        sH[r * D + j] = fmaxf(acc, 0.f);
    }
    __syncthreads();
    for (int i = j; i < D * D; i += blockDim.x) sW[i] = w2[i];
    sB[j] = b2[j];
    __syncthreads();

    for (int r = 0; r < RSEG; r++) {
        float acc = sB[j];
        #pragma unroll 8
        for (int k = 0; k < D; k++) acc += sH[r * D + k] * sW[k * D + j];
        g_rho[(seg0 + r) * D + j] = acc;
    }
}

// ---------------- k3: phi MLP, warp tile 16x128, H in registers ----------------
__global__ __launch_bounds__(NTHR, 1)
void k_phi(const float* __restrict__ x, const int* __restrict__ idx,
           const float* __restrict__ w1, const float* __restrict__ b1,
           const float* __restrict__ w2, const float* __restrict__ b2,
           float* __restrict__ out, int n) {
    extern __shared__ char smem[];
    const uint32_t sb = smem_u32(smem);
    int tid = threadIdx.x, wid = tid >> 5, lane = tid & 31;

    // ---- prologue: weights -> W^T bf16 hi/lo, biases ----
    for (int i = tid; i < D * D; i += NTHR) {      // i = k*128 + j
        int k = i >> 7, j = i & 127;
        uint32_t h, l, h2, l2;
        bsplit(w1[i], h, l);
        bsplit(w2[i], h2, l2);
        uint32_t o = (uint32_t)(j * WS + k) * 2;
        *(unsigned short*)(smem + OW1H + o) = (unsigned short)h;
        *(unsigned short*)(smem + OW1L + o) = (unsigned short)l;
        *(unsigned short*)(smem + OW2H + o) = (unsigned short)h2;
        *(unsigned short*)(smem + OW2L + o) = (unsigned short)l2;
    }
    if (tid < D) {
        ((float*)(smem + OB1))[tid] = b1[tid];
        ((float*)(smem + OB2))[tid] = b2[tid];
    }

    const float* sB1 = (const float*)(smem + OB1);
    const float* sB2 = (const float*)(smem + OB2);
    int* sIdx = (int*)(smem + OIDX);

    // ldmatrix bases:
    // A (16 rows of this warp): lanes 0-15 -> rows, lanes 16-31 -> +16B (k8-15)
    const uint32_t aRow = (uint32_t)(wid * 16 + (lane & 15)) * WS2
                        + (uint32_t)((lane >> 4) << 4);
    // B (n-major W^T): covers n16 x k16 per ldsm_x4
    const uint32_t bRow = (uint32_t)((lane & 7) + ((lane >> 4) << 3)) * WS2
                        + (uint32_t)(((lane >> 3) & 1) << 4);

    const int ntiles = (n + BM - 1) / BM;

    for (int tile = blockIdx.x; tile < ntiles; tile += gridDim.x) {
        long base = (long)tile * BM;
        __syncthreads();   // X buffer from previous tile fully consumed

        // ---- stage X tile -> bf16 hi/lo ----
        const float4* xv = (const float4*)x;
        #pragma unroll
        for (int it = 0; it < 16; ++it) {
            int i = it * NTHR + tid;          // 0..4095 float4 slots
            int m = i >> 5, kq = i & 31;
            float4 v = make_float4(0.f, 0.f, 0.f, 0.f);
            if (base + m < n) v = xv[(base + m) * 32 + kq];
            uint32_t h0,l0,h1,l1,h2,l2,h3,l3;
            bsplit(v.x,h0,l0); bsplit(v.y,h1,l1); bsplit(v.z,h2,l2); bsplit(v.w,h3,l3);
            uint32_t o = (uint32_t)(m * WS + kq * 4) * 2;
            *(uint2*)(smem + OXH + o) = make_uint2(h0 | (h1 << 16), h2 | (h3 << 16));
            *(uint2*)(smem + OXL + o) = make_uint2(l0 | (l1 << 16), l2 | (l3 << 16));
        }
        if (tid < BM) {
            int s = 0;
            if (base + tid < n) s = idx[base + tid];
            sIdx[tid] = s;
        }
        __syncthreads();

        // ---- layer 1: acc[nt] over 16 n8-tiles, 3-pass split ----
        float acc[16][4];
        #pragma unroll
        for (int a = 0; a < 16; a++)
            #pragma unroll
            for (int c = 0; c < 4; c++) acc[a][c] = 0.f;

        #pragma unroll
        for (int k = 0; k < 8; k++) {
            uint32_t ahf[4], alf[4];
            ldsm_x4(ahf, sb + OXH + aRow + k * 32);
            ldsm_x4(alf, sb + OXL + aRow + k * 32);
            #pragma unroll
            for (int np = 0; np < 8; np++) {
                uint32_t bh[4], bl[4];
                ldsm_x4(bh, sb + OW1H + bRow + np * 16 * WS2 + k * 32);
                ldsm_x4(bl, sb + OW1L + bRow + np * 16 * WS2 + k * 32);
                mma_bf16(acc[2*np],   ahf, bh);
                mma_bf16(acc[2*np+1], ahf, bh + 2);
                mma_bf16(acc[2*np],   ahf, bl);
                mma_bf16(acc[2*np+1], ahf, bl + 2);
                mma_bf16(acc[2*np],   alf, bh);
                mma_bf16(acc[2*np+1], alf, bh + 2);
            }
        }

        // ---- epilogue 1 (registers only): relu(.+b1) -> A fragments hi/lo ----
        // C-fragments of n-tiles (2kt, 2kt+1) form the A fragment for k-tile kt.
        uint32_t ah[8][4], al[8][4];
        #pragma unroll
        for (int kt = 0; kt < 8; kt++) {
            #pragma unroll
            for (int half = 0; half < 2; half++) {
                int nt = 2 * kt + half;
                int col = nt * 8 + (lane & 3) * 2;
                float v0 = fmaxf(acc[nt][0] + sB1[col],     0.f);
                float v1 = fmaxf(acc[nt][1] + sB1[col + 1], 0.f);
                float v2 = fmaxf(acc[nt][2] + sB1[col],     0.f);
                float v3 = fmaxf(acc[nt][3] + sB1[col + 1], 0.f);
                uint32_t h0,l0,h1,l1,h2,l2,h3,l3;
                bsplit(v0,h0,l0); bsplit(v1,h1,l1);
                bsplit(v2,h2,l2); bsplit(v3,h3,l3);
                ah[kt][2*half]     = h0 | (h1 << 16);
                ah[kt][2*half + 1] = h2 | (h3 << 16);
                al[kt][2*half]     = l0 | (l1 << 16);
                al[kt][2*half + 1] = l2 | (l3 << 16);
            }
        }

        // ---- layer 2: A from registers, B from smem ----
        #pragma unroll
        for (int a = 0; a < 16; a++)
            #pragma unroll
            for (int c = 0; c < 4; c++) acc[a][c] = 0.f;

        #pragma unroll
        for (int k = 0; k < 8; k++) {
            #pragma unroll
            for (int np = 0; np < 8; np++) {
                uint32_t bh[4], bl[4];
                ldsm_x4(bh, sb + OW2H + bRow + np * 16 * WS2 + k * 32);
                ldsm_x4(bl, sb + OW2L + bRow + np * 16 * WS2 + k * 32);
                mma_bf16(acc[2*np],   ah[k], bh);
                mma_bf16(acc[2*np+1], ah[k], bh + 2);
                mma_bf16(acc[2*np],   ah[k], bl);
                mma_bf16(acc[2*np+1], ah[k], bl + 2);
                mma_bf16(acc[2*np],   al[k], bh);
                mma_bf16(acc[2*np+1], al[k], bh + 2);
            }
        }

        // ---- writeout: + b2 + rho[idx], straight from fragments ----
        int r0 = wid * 16 + (lane >> 2);
        #pragma unroll
        for (int half = 0; half < 2; half++) {
            int row = r0 + half * 8;
            long grow = base + row;
            if (grow < n) {
                int seg = sIdx[row];
                const float* rrow = &g_rho[(long)seg * D];
                float* orow = &out[grow * D];
                #pragma unroll
                for (int nt = 0; nt < 16; nt++) {
                    int col = nt * 8 + (lane & 3) * 2;
                    float2 g = *(const float2*)&rrow[col];
                    float2 o;
                    o.x = acc[nt][2*half]     + sB2[col]     + g.x;
                    o.y = acc[nt][2*half + 1] + sB2[col + 1] + g.y;
                    *(float2*)&orow[col] = o;
                }
            }
        }
    }
}

// ---------------- launch --------------------------------------------------------
extern "C" void kernel_launch(void* const* d_in, const int* in_sizes, int n_in,
                              void* d_out, int out_size) {
    const float* x      = (const float*)d_in[0];
    const int*   idx    = (const int*)  d_in[1];
    const float* phi_w1 = (const float*)d_in[2];
    const float* phi_b1 = (const float*)d_in[3];
    const float* phi_w2 = (const float*)d_in[4];
    const float* phi_b2 = (const float*)d_in[5];
    const float* rho_w1 = (const float*)d_in[6];
    const float* rho_b1 = (const float*)d_in[7];
    const float* rho_w2 = (const float*)d_in[8];
    const float* rho_b2 = (const float*)d_in[9];
    float* out = (float*)d_out;
    int n = in_sizes[1];

    size_t smem_rho = (size_t)(D * D + 2 * RSEG * D + D) * sizeof(float);
    cudaFuncSetAttribute(k_rho, cudaFuncAttributeMaxDynamicSharedMemorySize,
                         (int)smem_rho);
    cudaFuncSetAttribute(k_phi, cudaFuncAttributeMaxDynamicSharedMemorySize,
                         SMEM_PHI);

    k_zero<<<(NSEG * D / 4 + 255) / 256, 256>>>();

    int segsum_blocks = (n + CH - 1) / CH;
    k_segsum<<<segsum_blocks, 128>>>(x, idx, n);

    k_rho<<<NSEG / RSEG, 128, smem_rho>>>(rho_w1, rho_b1, rho_w2, rho_b2);

    k_phi<<<152, NTHR, SMEM_PHI>>>(x, idx, phi_w1, phi_b1, phi_w2, phi_b2,
                                   out, n);
}

// round 6
// speedup vs baseline: 1.2260x; 1.2260x over previous
#include <cuda_runtime.h>
#include <cuda_bf16.h>
#include <cstdint>

#define D     128
#define NSEG  4096
#define BM    96
#define NTHR  384
#define CH    512
#define RSEG  32

#define WS    136            // padded bf16 row stride (272B, 16B multiple)
#define WS2   (WS * 2)
#define XTILE (BM * WS2)     // 26112 B  (X: 96 rows)
#define WTILE (D * WS2)      // 34816 B  (W: 128 rows)

// smem byte offsets
#define OXH  0
#define OXL  (XTILE)
#define OW1H (2 * XTILE)
#define OW1L (2 * XTILE + WTILE)
#define OW2H (2 * XTILE + 2 * WTILE)
#define OW2L (2 * XTILE + 3 * WTILE)
#define OB1  (2 * XTILE + 4 * WTILE)
#define OB2  (OB1 + 512)
#define OIDX (OB1 + 1024)
#define SMEM_PHI (OB1 + 1536)

// ---------------- scratch ----------------------------------------------------
__device__ float g_xsum[NSEG * D];
__device__ float g_rho [NSEG * D];

// ---------------- helpers ----------------------------------------------------
__device__ __forceinline__ uint32_t smem_u32(const void* p) {
    uint32_t a;
    asm("{ .reg .u64 t; cvta.to.shared.u64 t, %1; cvt.u32.u64 %0, t; }"
        : "=r"(a) : "l"(p));
    return a;
}
__device__ __forceinline__ void ldsm_x4(uint32_t r[4], uint32_t addr) {
    asm volatile("ldmatrix.sync.aligned.m8n8.x4.shared.b16 {%0,%1,%2,%3}, [%4];"
                 : "=r"(r[0]), "=r"(r[1]), "=r"(r[2]), "=r"(r[3]) : "r"(addr));
}
__device__ __forceinline__ void mma_bf16(float c[4], const uint32_t a[4],
                                         const uint32_t* b) {
    asm volatile("mma.sync.aligned.m16n8k16.row.col.f32.bf16.bf16.f32 "
                 "{%0,%1,%2,%3}, {%4,%5,%6,%7}, {%8,%9}, {%0,%1,%2,%3};"
                 : "+f"(c[0]), "+f"(c[1]), "+f"(c[2]), "+f"(c[3])
                 : "r"(a[0]), "r"(a[1]), "r"(a[2]), "r"(a[3]),
                   "r"(b[0]), "r"(b[1]));
}
__device__ __forceinline__ void bsplit(float v, uint32_t& h, uint32_t& l) {
    __nv_bfloat16 bh = __float2bfloat16(v);
    h = (uint32_t)__bfloat16_as_ushort(bh);
    float r = v - __bfloat162float(bh);
    l = (uint32_t)__bfloat16_as_ushort(__float2bfloat16(r));
}

// ---------------- k0: zero ---------------------------------------------------
__global__ void k_zero() {
    int i = blockIdx.x * blockDim.x + threadIdx.x;
    if (i < NSEG * D / 4)
        reinterpret_cast<float4*>(g_xsum)[i] = make_float4(0.f, 0.f, 0.f, 0.f);
}

// ---------------- k1: segment sum (idx sorted) --------------------------------
__global__ void k_segsum(const float* __restrict__ x,
                         const int*   __restrict__ idx, int n) {
    int f = threadIdx.x;
    long start = (long)blockIdx.x * CH;
    if (start >= n) return;
    long end = start + CH; if (end > n) end = n;

    int   cur = __ldg(&idx[start]);
    float acc = 0.f;
    long nn = start;
    for (; nn + 8 <= end; nn += 8) {
        float v[8]; int s[8];
        #pragma unroll
        for (int u = 0; u < 8; u++) {
            s[u] = __ldg(&idx[nn + u]);
            v[u] = __ldg(&x[(nn + u) * D + f]);
        }
        #pragma unroll
        for (int u = 0; u < 8; u++) {
            if (s[u] != cur) {
                atomicAdd(&g_xsum[(long)cur * D + f], acc);
                acc = 0.f; cur = s[u];
            }
            acc += v[u];
        }
    }
    for (; nn < end; ++nn) {
        int s = __ldg(&idx[nn]);
        float v = __ldg(&x[nn * D + f]);
        if (s != cur) {
            atomicAdd(&g_xsum[(long)cur * D + f], acc);
            acc = 0.f; cur = s;
        }
        acc += v;
    }
    atomicAdd(&g_xsum[(long)cur * D + f], acc);
}

// ---------------- k2: rho MLP on segment sums ----------------------------------
__global__ void k_rho(const float* __restrict__ w1, const float* __restrict__ b1,
                      const float* __restrict__ w2, const float* __restrict__ b2) {
    extern __shared__ float sm[];
    float* sW = sm;
    float* sX = sW + D * D;
    float* sH = sX + RSEG * D;
    float* sB = sH + RSEG * D;
    int j = threadIdx.x;
    int seg0 = blockIdx.x * RSEG;

    for (int r = 0; r < RSEG; r++)
        sX[r * D + j] = g_xsum[(seg0 + r) * D + j];
    for (int i = j; i < D * D; i += blockDim.x) sW[i] = w1[i];
    sB[j] = b1[j];
    __syncthreads();

    for (int r = 0; r < RSEG; r++) {
        float acc = sB[j];
        #pragma unroll 8
        for (int k = 0; k < D; k++) acc += sX[r * D + k] * sW[k * D + j];
        sH[r * D + j] = fmaxf(acc, 0.f);
    }
    __syncthreads();
    for (int i = j; i < D * D; i += blockDim.x) sW[i] = w2[i];
    sB[j] = b2[j];
    __syncthreads();

    for (int r = 0; r < RSEG; r++) {
        float acc = sB[j];
        #pragma unroll 8
        for (int k = 0; k < D; k++) acc += sH[r * D + k] * sW[k * D + j];
        g_rho[(seg0 + r) * D + j] = acc;
    }
}

// ---------------- pipelined 3-pass split GEMM, warp tile 32x32 -----------------
// A at (aH,aL): [96 x 128] bf16, stride WS.  B at (bH,bL): W^T [j][k], stride WS.
__device__ __forceinline__ void mma_layer(uint32_t sb, uint32_t aH, uint32_t aL,
                                          uint32_t bH, uint32_t bL,
                                          uint32_t aRow, uint32_t bRow,
                                          float acc[2][4][4]) {
    uint32_t ah[2][2][4], al[2][2][4];   // [k&1][mt][4]
    uint32_t bh[2][4],    bl[2][4];      // [np][4]

    // prologue: A(k=0), B(k=0, np=0)
    ldsm_x4(ah[0][0], sb + aH + aRow);
    ldsm_x4(ah[0][1], sb + aH + aRow + 16 * WS2);
    ldsm_x4(al[0][0], sb + aL + aRow);
    ldsm_x4(al[0][1], sb + aL + aRow + 16 * WS2);
    ldsm_x4(bh[0], sb + bH + bRow);
    ldsm_x4(bl[0], sb + bL + bRow);

    #pragma unroll
    for (int k = 0; k < 8; k++) {
        const int ka = k & 1, kn = ka ^ 1;
        // prefetch B(k, np=1)
        ldsm_x4(bh[1], sb + bH + bRow + 16 * WS2 + k * 32);
        ldsm_x4(bl[1], sb + bL + bRow + 16 * WS2 + k * 32);
        // prefetch A(k+1)
        if (k < 7) {
            ldsm_x4(ah[kn][0], sb + aH + aRow + (k + 1) * 32);
            ldsm_x4(ah[kn][1], sb + aH + aRow + 16 * WS2 + (k + 1) * 32);
            ldsm_x4(al[kn][0], sb + aL + aRow + (k + 1) * 32);
            ldsm_x4(al[kn][1], sb + aL + aRow + 16 * WS2 + (k + 1) * 32);
        }
        // MMAs np=0 (uses bh[0]/bl[0] loaded one step earlier)
        #pragma unroll
        for (int mt = 0; mt < 2; mt++) {
            mma_bf16(acc[mt][0], ah[ka][mt], bh[0]);
            mma_bf16(acc[mt][1], ah[ka][mt], bh[0] + 2);
            mma_bf16(acc[mt][0], ah[ka][mt], bl[0]);
            mma_bf16(acc[mt][1], ah[ka][mt], bl[0] + 2);
            mma_bf16(acc[mt][0], al[ka][mt], bh[0]);
            mma_bf16(acc[mt][1], al[ka][mt], bh[0] + 2);
        }
        // prefetch B(k+1, np=0)
        if (k < 7) {
            ldsm_x4(bh[0], sb + bH + bRow + (k + 1) * 32);
            ldsm_x4(bl[0], sb + bL + bRow + (k + 1) * 32);
        }
        // MMAs np=1
        #pragma unroll
        for (int mt = 0; mt < 2; mt++) {
            mma_bf16(acc[mt][2], ah[ka][mt], bh[1]);
            mma_bf16(acc[mt][3], ah[ka][mt], bh[1] + 2);
            mma_bf16(acc[mt][2], ah[ka][mt], bl[1]);
            mma_bf16(acc[mt][3], ah[ka][mt], bl[1] + 2);
            mma_bf16(acc[mt][2], al[ka][mt], bh[1]);
            mma_bf16(acc[mt][3], al[ka][mt], bh[1] + 2);
        }
    }
}

// ---------------- k3: phi MLP (HMMA, pipelined) + fused rho gather --------------
__global__ __launch_bounds__(NTHR, 1)
void k_phi(const float* __restrict__ x, const int* __restrict__ idx,
           const float* __restrict__ w1, const float* __restrict__ b1,
           const float* __restrict__ w2, const float* __restrict__ b2,
           float* __restrict__ out, int n) {
    extern __shared__ char smem[];
    const uint32_t sb = smem_u32(smem);
    int tid = threadIdx.x, wid = tid >> 5, lane = tid & 31;
    int wm = wid >> 2, wn = wid & 3;      // 3 x 4 warp grid, warp tile 32x32

    // ---- prologue: weights -> W^T bf16 hi/lo, biases ----
    for (int i = tid; i < D * D; i += NTHR) {      // i = k*128 + j
        int k = i >> 7, j = i & 127;
        uint32_t h, l, h2, l2;
        bsplit(w1[i], h, l);
        bsplit(w2[i], h2, l2);
        uint32_t o = (uint32_t)(j * WS + k) * 2;
        *(unsigned short*)(smem + OW1H + o) = (unsigned short)h;
        *(unsigned short*)(smem + OW1L + o) = (unsigned short)l;
        *(unsigned short*)(smem + OW2H + o) = (unsigned short)h2;
        *(unsigned short*)(smem + OW2L + o) = (unsigned short)l2;
    }
    if (tid < D) {
        ((float*)(smem + OB1))[tid] = b1[tid];
        ((float*)(smem + OB2))[tid] = b2[tid];
    }

    const float* sB1 = (const float*)(smem + OB1);
    const float* sB2 = (const float*)(smem + OB2);
    int* sIdx = (int*)(smem + OIDX);

    // per-warp ldmatrix row bases (bytes)
    const uint32_t aRow = (uint32_t)(wm * 32 + (lane & 15)) * WS2
                        + (uint32_t)((lane >> 4) << 4);
    const uint32_t bRow = (uint32_t)(wn * 32 + (lane & 7) + ((lane >> 4) << 3)) * WS2
                        + (uint32_t)(((lane >> 3) & 1) << 4);

    const int ntiles = (n + BM - 1) / BM;

    for (int tile = blockIdx.x; tile < ntiles; tile += gridDim.x) {
        long base = (long)tile * BM;
        __syncthreads();   // previous tile fully consumed

        // ---- stage X tile -> bf16 hi/lo ----
        const float4* xv = (const float4*)x;
        #pragma unroll
        for (int it = 0; it < 8; ++it) {
            int i = it * NTHR + tid;          // 0..3071 float4 slots
            int m = i >> 5, kq = i & 31;
            float4 v = make_float4(0.f, 0.f, 0.f, 0.f);
            if (base + m < n) v = xv[(base + m) * 32 + kq];
            uint32_t h0,l0,h1,l1,h2,l2,h3,l3;
            bsplit(v.x,h0,l0); bsplit(v.y,h1,l1); bsplit(v.z,h2,l2); bsplit(v.w,h3,l3);
            uint32_t o = (uint32_t)(m * WS + kq * 4) * 2;
            *(uint2*)(smem + OXH + o) = make_uint2(h0 | (h1 << 16), h2 | (h3 << 16));
            *(uint2*)(smem + OXL + o) = make_uint2(l0 | (l1 << 16), l2 | (l3 << 16));
        }
        if (tid < BM) {
            int s = 0;
            if (base + tid < n) s = idx[base + tid];
            sIdx[tid] = s;
        }
        __syncthreads();

        // ---- layer 1 ----
        float acc[2][4][4];
        #pragma unroll
        for (int a = 0; a < 2; a++)
            #pragma unroll
            for (int b = 0; b < 4; b++)
                #pragma unroll
                for (int c = 0; c < 4; c++) acc[a][b][c] = 0.f;
        mma_layer(sb, OXH, OXL, OW1H, OW1L, aRow, bRow, acc);
        __syncthreads();   // all warps done reading X

        // ---- epilogue 1: relu(.+b1) -> bf16 hi/lo back into X buffers ----
        #pragma unroll
        for (int mt = 0; mt < 2; mt++) {
            int r0 = wm * 32 + mt * 16 + (lane >> 2);
            #pragma unroll
            for (int nt = 0; nt < 4; nt++) {
                int col = wn * 32 + nt * 8 + (lane & 3) * 2;
                float* c = acc[mt][nt];
                float v0 = fmaxf(c[0] + sB1[col],     0.f);
                float v1 = fmaxf(c[1] + sB1[col + 1], 0.f);
                float v2 = fmaxf(c[2] + sB1[col],     0.f);
                float v3 = fmaxf(c[3] + sB1[col + 1], 0.f);
                uint32_t h0,l0,h1,l1,h2,l2,h3,l3;
                bsplit(v0,h0,l0); bsplit(v1,h1,l1);
                bsplit(v2,h2,l2); bsplit(v3,h3,l3);
                uint32_t oA = (uint32_t)(r0 * WS + col) * 2;
                uint32_t oB = (uint32_t)((r0 + 8) * WS + col) * 2;
                *(uint32_t*)(smem + OXH + oA) = h0 | (h1 << 16);
                *(uint32_t*)(smem + OXL + oA) = l0 | (l1 << 16);
                *(uint32_t*)(smem + OXH + oB) = h2 | (h3 << 16);
                *(uint32_t*)(smem + OXL + oB) = l2 | (l3 << 16);
            }
        }
        __syncthreads();

        // ---- layer 2 ----
        #pragma unroll
        for (int a = 0; a < 2; a++)
            #pragma unroll
            for (int b = 0; b < 4; b++)
                #pragma unroll
                for (int c = 0; c < 4; c++) acc[a][b][c] = 0.f;
        mma_layer(sb, OXH, OXL, OW2H, OW2L, aRow, bRow, acc);

        // ---- writeout: + b2 + rho[idx], straight from fragments ----
        #pragma unroll
        for (int mt = 0; mt < 2; mt++) {
            int rl = wm * 32 + mt * 16 + (lane >> 2);
            #pragma unroll
            for (int half = 0; half < 2; half++) {
                int row = rl + half * 8;
                long grow = base + row;
                if (grow < n) {
                    int seg = sIdx[row];
                    #pragma unroll
                    for (int nt = 0; nt < 4; nt++) {
                        int col = wn * 32 + nt * 8 + (lane & 3) * 2;
                        float* c = acc[mt][nt];
                        float2 g = *(const float2*)&g_rho[(long)seg * D + col];
                        float2 o;
                        o.x = c[2 * half]     + sB2[col]     + g.x;
                        o.y = c[2 * half + 1] + sB2[col + 1] + g.y;
                        *(float2*)&out[grow * D + col] = o;
                    }
                }
            }
        }
    }
}

// ---------------- launch --------------------------------------------------------
extern "C" void kernel_launch(void* const* d_in, const int* in_sizes, int n_in,
                              void* d_out, int out_size) {
    const float* x      = (const float*)d_in[0];
    const int*   idx    = (const int*)  d_in[1];
    const float* phi_w1 = (const float*)d_in[2];
    const float* phi_b1 = (const float*)d_in[3];
    const float* phi_w2 = (const float*)d_in[4];
    const float* phi_b2 = (const float*)d_in[5];
    const float* rho_w1 = (const float*)d_in[6];
    const float* rho_b1 = (const float*)d_in[7];
    const float* rho_w2 = (const float*)d_in[8];
    const float* rho_b2 = (const float*)d_in[9];
    float* out = (float*)d_out;
    int n = in_sizes[1];

    size_t smem_rho = (size_t)(D * D + 2 * RSEG * D + D) * sizeof(float);
    cudaFuncSetAttribute(k_rho, cudaFuncAttributeMaxDynamicSharedMemorySize,
                         (int)smem_rho);
    cudaFuncSetAttribute(k_phi, cudaFuncAttributeMaxDynamicSharedMemorySize,
                         SMEM_PHI);

    k_zero<<<(NSEG * D / 4 + 255) / 256, 256>>>();

    int segsum_blocks = (n + CH - 1) / CH;
    k_segsum<<<segsum_blocks, 128>>>(x, idx, n);

    k_rho<<<NSEG / RSEG, 128, smem_rho>>>(rho_w1, rho_b1, rho_w2, rho_b2);

    k_phi<<<152, NTHR, SMEM_PHI>>>(x, idx, phi_w1, phi_b1, phi_w2, phi_b2,
                                   out, n);
}

// round 7
// speedup vs baseline: 1.2580x; 1.0261x over previous
#include <cuda_runtime.h>
#include <cuda_bf16.h>
#include <cstdint>

#define D     128
#define NSEG  4096
#define BM    96
#define NTHR  768
#define CH    512
#define RSEG  32

#define WS    136            // padded bf16 row stride (272B, 16B multiple)
#define WS2   (WS * 2)
#define XTILE (BM * WS2)     // 26112 B  (X: 96 rows)
#define WTILE (D * WS2)      // 34816 B  (W: 128 rows)

// smem byte offsets
#define OXH  0
#define OXL  (XTILE)
#define OW1H (2 * XTILE)
#define OW1L (2 * XTILE + WTILE)
#define OW2H (2 * XTILE + 2 * WTILE)
#define OW2L (2 * XTILE + 3 * WTILE)
#define OB1  (2 * XTILE + 4 * WTILE)
#define OB2  (OB1 + 512)
#define OIDX (OB1 + 1024)
#define SMEM_PHI (OB1 + 1536)

// ---------------- scratch ----------------------------------------------------
__device__ float g_xsum[NSEG * D];
__device__ float g_rho [NSEG * D];

// ---------------- helpers ----------------------------------------------------
__device__ __forceinline__ uint32_t smem_u32(const void* p) {
    uint32_t a;
    asm("{ .reg .u64 t; cvta.to.shared.u64 t, %1; cvt.u32.u64 %0, t; }"
        : "=r"(a) : "l"(p));
    return a;
}
__device__ __forceinline__ void ldsm_x4(uint32_t r[4], uint32_t addr) {
    asm volatile("ldmatrix.sync.aligned.m8n8.x4.shared.b16 {%0,%1,%2,%3}, [%4];"
                 : "=r"(r[0]), "=r"(r[1]), "=r"(r[2]), "=r"(r[3]) : "r"(addr));
}
__device__ __forceinline__ void mma_bf16(float c[4], const uint32_t a[4],
                                         const uint32_t* b) {
    asm volatile("mma.sync.aligned.m16n8k16.row.col.f32.bf16.bf16.f32 "
                 "{%0,%1,%2,%3}, {%4,%5,%6,%7}, {%8,%9}, {%0,%1,%2,%3};"
                 : "+f"(c[0]), "+f"(c[1]), "+f"(c[2]), "+f"(c[3])
                 : "r"(a[0]), "r"(a[1]), "r"(a[2]), "r"(a[3]),
                   "r"(b[0]), "r"(b[1]));
}
__device__ __forceinline__ void bsplit(float v, uint32_t& h, uint32_t& l) {
    __nv_bfloat16 bh = __float2bfloat16(v);
    h = (uint32_t)__bfloat16_as_ushort(bh);
    float r = v - __bfloat162float(bh);
    l = (uint32_t)__bfloat16_as_ushort(__float2bfloat16(r));
}

// ---------------- k0: zero ---------------------------------------------------
__global__ void k_zero() {
    int i = blockIdx.x * blockDim.x + threadIdx.x;
    if (i < NSEG * D / 4)
        reinterpret_cast<float4*>(g_xsum)[i] = make_float4(0.f, 0.f, 0.f, 0.f);
}

// ---------------- k1: segment sum (idx sorted) --------------------------------
__global__ void k_segsum(const float* __restrict__ x,
                         const int*   __restrict__ idx, int n) {
    int f = threadIdx.x;
    long start = (long)blockIdx.x * CH;
    if (start >= n) return;
    long end = start + CH; if (end > n) end = n;

    int   cur = __ldg(&idx[start]);
    float acc = 0.f;
    long nn = start;
    for (; nn + 8 <= end; nn += 8) {
        float v[8]; int s[8];
        #pragma unroll
        for (int u = 0; u < 8; u++) {
            s[u] = __ldg(&idx[nn + u]);
            v[u] = __ldg(&x[(nn + u) * D + f]);
        }
        #pragma unroll
        for (int u = 0; u < 8; u++) {
            if (s[u] != cur) {
                atomicAdd(&g_xsum[(long)cur * D + f], acc);
                acc = 0.f; cur = s[u];
            }
            acc += v[u];
        }
    }
    for (; nn < end; ++nn) {
        int s = __ldg(&idx[nn]);
        float v = __ldg(&x[nn * D + f]);
        if (s != cur) {
            atomicAdd(&g_xsum[(long)cur * D + f], acc);
            acc = 0.f; cur = s;
        }
        acc += v;
    }
    atomicAdd(&g_xsum[(long)cur * D + f], acc);
}

// ---------------- k2: rho MLP on segment sums ----------------------------------
__global__ void k_rho(const float* __restrict__ w1, const float* __restrict__ b1,
                      const float* __restrict__ w2, const float* __restrict__ b2) {
    extern __shared__ float sm[];
    float* sW = sm;
    float* sX = sW + D * D;
    float* sH = sX + RSEG * D;
    float* sB = sH + RSEG * D;
    int j = threadIdx.x;
    int seg0 = blockIdx.x * RSEG;

    for (int r = 0; r < RSEG; r++)
        sX[r * D + j] = g_xsum[(seg0 + r) * D + j];
    for (int i = j; i < D * D; i += blockDim.x) sW[i] = w1[i];
    sB[j] = b1[j];
    __syncthreads();

    for (int r = 0; r < RSEG; r++) {
        float acc = sB[j];
        #pragma unroll 8
        for (int k = 0; k < D; k++) acc += sX[r * D + k] * sW[k * D + j];
        sH[r * D + j] = fmaxf(acc, 0.f);
    }
    __syncthreads();
    for (int i = j; i < D * D; i += blockDim.x) sW[i] = w2[i];
    sB[j] = b2[j];
    __syncthreads();

    for (int r = 0; r < RSEG; r++) {
        float acc = sB[j];
        #pragma unroll 8
        for (int k = 0; k < D; k++) acc += sH[r * D + k] * sW[k * D + j];
        g_rho[(seg0 + r) * D + j] = acc;
    }
}

// ---------------- 3-pass split GEMM, warp tile 16x32 (lean regs) ---------------
__device__ __forceinline__ void mma_layer(uint32_t sb, uint32_t aH, uint32_t aL,
                                          uint32_t bH, uint32_t bL,
                                          uint32_t aRow, uint32_t bRow,
                                          float acc[4][4]) {
    #pragma unroll
    for (int k = 0; k < 8; k++) {
        uint32_t ah[4], al[4];
        ldsm_x4(ah, sb + aH + aRow + k * 32);
        ldsm_x4(al, sb + aL + aRow + k * 32);
        #pragma unroll
        for (int np = 0; np < 2; np++) {
            uint32_t bh[4], bl[4];
            ldsm_x4(bh, sb + bH + bRow + np * 16 * WS2 + k * 32);
            ldsm_x4(bl, sb + bL + bRow + np * 16 * WS2 + k * 32);
            mma_bf16(acc[2*np],   ah, bh);
            mma_bf16(acc[2*np+1], ah, bh + 2);
            mma_bf16(acc[2*np],   ah, bl);
            mma_bf16(acc[2*np+1], ah, bl + 2);
            mma_bf16(acc[2*np],   al, bh);
            mma_bf16(acc[2*np+1], al, bh + 2);
        }
    }
}

// ---------------- k3: phi MLP (24 warps, warp tile 16x32) ----------------------
__global__ __launch_bounds__(NTHR, 1)
void k_phi(const float* __restrict__ x, const int* __restrict__ idx,
           const float* __restrict__ w1, const float* __restrict__ b1,
           const float* __restrict__ w2, const float* __restrict__ b2,
           float* __restrict__ out, int n) {
    extern __shared__ char smem[];
    const uint32_t sb = smem_u32(smem);
    int tid = threadIdx.x, wid = tid >> 5, lane = tid & 31;
    int wm = wid >> 2, wn = wid & 3;      // 6 x 4 warp grid, warp tile 16x32

    // ---- prologue: weights -> W^T bf16 hi/lo, biases ----
    for (int i = tid; i < D * D; i += NTHR) {      // i = k*128 + j
        int k = i >> 7, j = i & 127;
        uint32_t h, l, h2, l2;
        bsplit(w1[i], h, l);
        bsplit(w2[i], h2, l2);
        uint32_t o = (uint32_t)(j * WS + k) * 2;
        *(unsigned short*)(smem + OW1H + o) = (unsigned short)h;
        *(unsigned short*)(smem + OW1L + o) = (unsigned short)l;
        *(unsigned short*)(smem + OW2H + o) = (unsigned short)h2;
        *(unsigned short*)(smem + OW2L + o) = (unsigned short)l2;
    }
    if (tid < D) {
        ((float*)(smem + OB1))[tid] = b1[tid];
        ((float*)(smem + OB2))[tid] = b2[tid];
    }

    const float* sB1 = (const float*)(smem + OB1);
    const float* sB2 = (const float*)(smem + OB2);
    int* sIdx = (int*)(smem + OIDX);

    // per-warp ldmatrix row bases (bytes)
    const uint32_t aRow = (uint32_t)(wm * 16 + (lane & 15)) * WS2
                        + (uint32_t)((lane >> 4) << 4);
    const uint32_t bRow = (uint32_t)(wn * 32 + (lane & 7) + ((lane >> 4) << 3)) * WS2
                        + (uint32_t)(((lane >> 3) & 1) << 4);

    const int ntiles = (n + BM - 1) / BM;

    for (int tile = blockIdx.x; tile < ntiles; tile += gridDim.x) {
        long base = (long)tile * BM;
        __syncthreads();   // previous tile fully consumed

        // ---- stage X tile -> bf16 hi/lo ----
        const float4* xv = (const float4*)x;
        #pragma unroll
        for (int it = 0; it < 4; ++it) {
            int i = it * NTHR + tid;          // 0..3071 float4 slots
            int m = i >> 5, kq = i & 31;
            float4 v = make_float4(0.f, 0.f, 0.f, 0.f);
            if (base + m < n) v = xv[(base + m) * 32 + kq];
            uint32_t h0,l0,h1,l1,h2,l2,h3,l3;
            bsplit(v.x,h0,l0); bsplit(v.y,h1,l1); bsplit(v.z,h2,l2); bsplit(v.w,h3,l3);
            uint32_t o = (uint32_t)(m * WS + kq * 4) * 2;
            *(uint2*)(smem + OXH + o) = make_uint2(h0 | (h1 << 16), h2 | (h3 << 16));
            *(uint2*)(smem + OXL + o) = make_uint2(l0 | (l1 << 16), l2 | (l3 << 16));
        }
        if (tid < BM) {
            int s = 0;
            if (base + tid < n) s = idx[base + tid];
            sIdx[tid] = s;
        }
        __syncthreads();

        // ---- layer 1 ----
        float acc[4][4];
        #pragma unroll
        for (int b = 0; b < 4; b++)
            #pragma unroll
            for (int c = 0; c < 4; c++) acc[b][c] = 0.f;
        mma_layer(sb, OXH, OXL, OW1H, OW1L, aRow, bRow, acc);
        __syncthreads();   // all warps done reading X

        // ---- epilogue 1: relu(.+b1) -> bf16 hi/lo back into X buffers ----
        {
            int r0 = wm * 16 + (lane >> 2);
            #pragma unroll
            for (int nt = 0; nt < 4; nt++) {
                int col = wn * 32 + nt * 8 + (lane & 3) * 2;
                float* c = acc[nt];
                float v0 = fmaxf(c[0] + sB1[col],     0.f);
                float v1 = fmaxf(c[1] + sB1[col + 1], 0.f);
                float v2 = fmaxf(c[2] + sB1[col],     0.f);
                float v3 = fmaxf(c[3] + sB1[col + 1], 0.f);
                uint32_t h0,l0,h1,l1,h2,l2,h3,l3;
                bsplit(v0,h0,l0); bsplit(v1,h1,l1);
                bsplit(v2,h2,l2); bsplit(v3,h3,l3);
                uint32_t oA = (uint32_t)(r0 * WS + col) * 2;
                uint32_t oB = (uint32_t)((r0 + 8) * WS + col) * 2;
                *(uint32_t*)(smem + OXH + oA) = h0 | (h1 << 16);
                *(uint32_t*)(smem + OXL + oA) = l0 | (l1 << 16);
                *(uint32_t*)(smem + OXH + oB) = h2 | (h3 << 16);
                *(uint32_t*)(smem + OXL + oB) = l2 | (l3 << 16);
            }
        }
        __syncthreads();

        // ---- layer 2 ----
        #pragma unroll
        for (int b = 0; b < 4; b++)
            #pragma unroll
            for (int c = 0; c < 4; c++) acc[b][c] = 0.f;
        mma_layer(sb, OXH, OXL, OW2H, OW2L, aRow, bRow, acc);

        // ---- writeout: + b2 + rho[idx], straight from fragments ----
        {
            int rl = wm * 16 + (lane >> 2);
            #pragma unroll
            for (int half = 0; half < 2; half++) {
                int row = rl + half * 8;
                long grow = base + row;
                if (grow < n) {
                    int seg = sIdx[row];
                    const float* rrow = &g_rho[(long)seg * D];
                    float* orow = &out[grow * D];
                    #pragma unroll
                    for (int nt = 0; nt < 4; nt++) {
                        int col = wn * 32 + nt * 8 + (lane & 3) * 2;
                        float* c = acc[nt];
                        float2 g = *(const float2*)&rrow[col];
                        float2 o;
                        o.x = c[2 * half]     + sB2[col]     + g.x;
                        o.y = c[2 * half + 1] + sB2[col + 1] + g.y;
                        *(float2*)&orow[col] = o;
                    }
                }
            }
        }
    }
}

// ---------------- launch --------------------------------------------------------
extern "C" void kernel_launch(void* const* d_in, const int* in_sizes, int n_in,
                              void* d_out, int out_size) {
    const float* x      = (const float*)d_in[0];
    const int*   idx    = (const int*)  d_in[1];
    const float* phi_w1 = (const float*)d_in[2];
    const float* phi_b1 = (const float*)d_in[3];
    const float* phi_w2 = (const float*)d_in[4];
    const float* phi_b2 = (const float*)d_in[5];
    const float* rho_w1 = (const float*)d_in[6];
    const float* rho_b1 = (const float*)d_in[7];
    const float* rho_w2 = (const float*)d_in[8];
    const float* rho_b2 = (const float*)d_in[9];
    float* out = (float*)d_out;
    int n = in_sizes[1];

    size_t smem_rho = (size_t)(D * D + 2 * RSEG * D + D) * sizeof(float);
    cudaFuncSetAttribute(k_rho, cudaFuncAttributeMaxDynamicSharedMemorySize,
                         (int)smem_rho);
    cudaFuncSetAttribute(k_phi, cudaFuncAttributeMaxDynamicSharedMemorySize,
                         SMEM_PHI);

    k_zero<<<(NSEG * D / 4 + 255) / 256, 256>>>();

    int segsum_blocks = (n + CH - 1) / CH;
    k_segsum<<<segsum_blocks, 128>>>(x, idx, n);

    k_rho<<<NSEG / RSEG, 128, smem_rho>>>(rho_w1, rho_b1, rho_w2, rho_b2);

    k_phi<<<152, NTHR, SMEM_PHI>>>(x, idx, phi_w1, phi_b1, phi_w2, phi_b2,
                                   out, n);
}

// round 8
// speedup vs baseline: 1.9221x; 1.5279x over previous
#include <cuda_runtime.h>
#include <cuda_fp16.h>
#include <cstdint>

#define D     128
#define NSEG  4096
#define BM    128
#define NTHR  512
#define CH    512
#define RSEG  32

#define WS    136            // padded fp16 row stride (272B, 16B multiple)
#define WS2   (WS * 2)
#define XTILE (BM * WS2)     // 34816 B
#define WTILE (D * WS2)      // 34816 B

// smem byte offsets
#define OX   0
#define OW1  (XTILE)
#define OW2  (XTILE + WTILE)
#define OB1  (XTILE + 2 * WTILE)
#define OB2  (OB1 + 512)
#define OIDX (OB1 + 1024)
#define SMEM_PHI (OB1 + 1536)

// ---------------- scratch ----------------------------------------------------
__device__ float g_xsum[NSEG * D];
__device__ float g_rho [NSEG * D];

// ---------------- helpers ----------------------------------------------------
__device__ __forceinline__ uint32_t smem_u32(const void* p) {
    uint32_t a;
    asm("{ .reg .u64 t; cvta.to.shared.u64 t, %1; cvt.u32.u64 %0, t; }"
        : "=r"(a) : "l"(p));
    return a;
}
__device__ __forceinline__ void ldsm_x4(uint32_t r[4], uint32_t addr) {
    asm volatile("ldmatrix.sync.aligned.m8n8.x4.shared.b16 {%0,%1,%2,%3}, [%4];"
                 : "=r"(r[0]), "=r"(r[1]), "=r"(r[2]), "=r"(r[3]) : "r"(addr));
}
__device__ __forceinline__ void mma_f16(float c[4], const uint32_t a[4],
                                        const uint32_t* b) {
    asm volatile("mma.sync.aligned.m16n8k16.row.col.f32.f16.f16.f32 "
                 "{%0,%1,%2,%3}, {%4,%5,%6,%7}, {%8,%9}, {%0,%1,%2,%3};"
                 : "+f"(c[0]), "+f"(c[1]), "+f"(c[2]), "+f"(c[3])
                 : "r"(a[0]), "r"(a[1]), "r"(a[2]), "r"(a[3]),
                   "r"(b[0]), "r"(b[1]));
}
__device__ __forceinline__ uint32_t packh2(float a, float b) {
    __half2 h = __floats2half2_rn(a, b);
    return *(uint32_t*)&h;
}

// ---------------- k0: zero ---------------------------------------------------
__global__ void k_zero() {
    int i = blockIdx.x * blockDim.x + threadIdx.x;
    if (i < NSEG * D / 4)
        reinterpret_cast<float4*>(g_xsum)[i] = make_float4(0.f, 0.f, 0.f, 0.f);
}

// ---------------- k1: segment sum (idx sorted) --------------------------------
__global__ void k_segsum(const float* __restrict__ x,
                         const int*   __restrict__ idx, int n) {
    int f = threadIdx.x;
    long start = (long)blockIdx.x * CH;
    if (start >= n) return;
    long end = start + CH; if (end > n) end = n;

    int   cur = __ldg(&idx[start]);
    float acc = 0.f;
    long nn = start;
    for (; nn + 8 <= end; nn += 8) {
        float v[8]; int s[8];
        #pragma unroll
        for (int u = 0; u < 8; u++) {
            s[u] = __ldg(&idx[nn + u]);
            v[u] = __ldg(&x[(nn + u) * D + f]);
        }
        #pragma unroll
        for (int u = 0; u < 8; u++) {
            if (s[u] != cur) {
                atomicAdd(&g_xsum[(long)cur * D + f], acc);
                acc = 0.f; cur = s[u];
            }
            acc += v[u];
        }
    }
    for (; nn < end; ++nn) {
        int s = __ldg(&idx[nn]);
        float v = __ldg(&x[nn * D + f]);
        if (s != cur) {
            atomicAdd(&g_xsum[(long)cur * D + f], acc);
            acc = 0.f; cur = s;
        }
        acc += v;
    }
    atomicAdd(&g_xsum[(long)cur * D + f], acc);
}

// ---------------- k2: rho MLP on segment sums ----------------------------------
__global__ void k_rho(const float* __restrict__ w1, const float* __restrict__ b1,
                      const float* __restrict__ w2, const float* __restrict__ b2) {
    extern __shared__ float sm[];
    float* sW = sm;
    float* sX = sW + D * D;
    float* sH = sX + RSEG * D;
    float* sB = sH + RSEG * D;
    int j = threadIdx.x;
    int seg0 = blockIdx.x * RSEG;

    for (int r = 0; r < RSEG; r++)
        sX[r * D + j] = g_xsum[(seg0 + r) * D + j];
    for (int i = j; i < D * D; i += blockDim.x) sW[i] = w1[i];
    sB[j] = b1[j];
    __syncthreads();

    for (int r = 0; r < RSEG; r++) {
        float acc = sB[j];
        #pragma unroll 8
        for (int k = 0; k < D; k++) acc += sX[r * D + k] * sW[k * D + j];
        sH[r * D + j] = fmaxf(acc, 0.f);
    }
    __syncthreads();
    for (int i = j; i < D * D; i += blockDim.x) sW[i] = w2[i];
    sB[j] = b2[j];
    __syncthreads();

    for (int r = 0; r < RSEG; r++) {
        float acc = sB[j];
        #pragma unroll 8
        for (int k = 0; k < D; k++) acc += sH[r * D + k] * sW[k * D + j];
        g_rho[(seg0 + r) * D + j] = acc;
    }
}

// ---------------- single-pass fp16 GEMM, warp tile 32x32 ------------------------
// A at aOff: [128 x 128] fp16, stride WS.  B at bOff: W^T [j][k], stride WS.
__device__ __forceinline__ void mma_layer(uint32_t sb, uint32_t aOff, uint32_t bOff,
                                          uint32_t aRow, uint32_t bRow,
                                          float acc[2][4][4]) {
    #pragma unroll
    for (int k = 0; k < 8; k++) {
        uint32_t a0[4], a1[4];
        ldsm_x4(a0, sb + aOff + aRow + k * 32);
        ldsm_x4(a1, sb + aOff + aRow + 16 * WS2 + k * 32);
        #pragma unroll
        for (int np = 0; np < 2; np++) {
            uint32_t b[4];
            ldsm_x4(b, sb + bOff + bRow + np * 16 * WS2 + k * 32);
            mma_f16(acc[0][2*np],   a0, b);
            mma_f16(acc[0][2*np+1], a0, b + 2);
            mma_f16(acc[1][2*np],   a1, b);
            mma_f16(acc[1][2*np+1], a1, b + 2);
        }
    }
}

// ---------------- k3: phi MLP (fp16 HMMA) + fused rho gather --------------------
__global__ __launch_bounds__(NTHR, 1)
void k_phi(const float* __restrict__ x, const int* __restrict__ idx,
           const float* __restrict__ w1, const float* __restrict__ b1,
           const float* __restrict__ w2, const float* __restrict__ b2,
           float* __restrict__ out, int n) {
    extern __shared__ char smem[];
    const uint32_t sb = smem_u32(smem);
    int tid = threadIdx.x, wid = tid >> 5, lane = tid & 31;
    int wm = wid >> 2, wn = wid & 3;      // 4 x 4 warp grid, warp tile 32x32

    // ---- prologue: weights -> W^T fp16, biases ----
    for (int i = tid; i < D * D; i += NTHR) {      // i = k*128 + j
        int k = i >> 7, j = i & 127;
        uint32_t o = (uint32_t)(j * WS + k) * 2;
        *(__half*)(smem + OW1 + o) = __float2half_rn(w1[i]);
        *(__half*)(smem + OW2 + o) = __float2half_rn(w2[i]);
    }
    if (tid < D) {
        ((float*)(smem + OB1))[tid] = b1[tid];
        ((float*)(smem + OB2))[tid] = b2[tid];
    }

    const float* sB1 = (const float*)(smem + OB1);
    const float* sB2 = (const float*)(smem + OB2);
    int* sIdx = (int*)(smem + OIDX);

    // per-warp ldmatrix row bases (bytes)
    const uint32_t aRow = (uint32_t)(wm * 32 + (lane & 15)) * WS2
                        + (uint32_t)((lane >> 4) << 4);
    const uint32_t bRow = (uint32_t)(wn * 32 + (lane & 7) + ((lane >> 4) << 3)) * WS2
                        + (uint32_t)(((lane >> 3) & 1) << 4);

    const int ntiles = (n + BM - 1) / BM;

    for (int tile = blockIdx.x; tile < ntiles; tile += gridDim.x) {
        long base = (long)tile * BM;
        __syncthreads();   // previous tile fully consumed

        // ---- stage X tile -> fp16 ----
        const float4* xv = (const float4*)x;
        #pragma unroll
        for (int it = 0; it < 8; ++it) {
            int i = it * NTHR + tid;          // 0..4095 float4 slots
            int m = i >> 5, kq = i & 31;
            float4 v = make_float4(0.f, 0.f, 0.f, 0.f);
            if (base + m < n) v = xv[(base + m) * 32 + kq];
            uint32_t o = (uint32_t)(m * WS + kq * 4) * 2;
            *(uint2*)(smem + OX + o) = make_uint2(packh2(v.x, v.y),
                                                  packh2(v.z, v.w));
        }
        if (tid < BM) {
            int s = 0;
            if (base + tid < n) s = idx[base + tid];
            sIdx[tid] = s;
        }
        __syncthreads();

        // ---- layer 1 ----
        float acc[2][4][4];
        #pragma unroll
        for (int a = 0; a < 2; a++)
            #pragma unroll
            for (int b = 0; b < 4; b++)
                #pragma unroll
                for (int c = 0; c < 4; c++) acc[a][b][c] = 0.f;
        mma_layer(sb, OX, OW1, aRow, bRow, acc);
        __syncthreads();   // all warps done reading X

        // ---- epilogue 1: relu(.+b1) -> fp16 back into X buffer ----
        #pragma unroll
        for (int mt = 0; mt < 2; mt++) {
            int r0 = wm * 32 + mt * 16 + (lane >> 2);
            #pragma unroll
            for (int nt = 0; nt < 4; nt++) {
                int col = wn * 32 + nt * 8 + (lane & 3) * 2;
                float* c = acc[mt][nt];
                float v0 = fmaxf(c[0] + sB1[col],     0.f);
                float v1 = fmaxf(c[1] + sB1[col + 1], 0.f);
                float v2 = fmaxf(c[2] + sB1[col],     0.f);
                float v3 = fmaxf(c[3] + sB1[col + 1], 0.f);
                *(uint32_t*)(smem + OX + (uint32_t)(r0 * WS + col) * 2)
                    = packh2(v0, v1);
                *(uint32_t*)(smem + OX + (uint32_t)((r0 + 8) * WS + col) * 2)
                    = packh2(v2, v3);
            }
        }
        __syncthreads();

        // ---- layer 2 ----
        #pragma unroll
        for (int a = 0; a < 2; a++)
            #pragma unroll
            for (int b = 0; b < 4; b++)
                #pragma unroll
                for (int c = 0; c < 4; c++) acc[a][b][c] = 0.f;
        mma_layer(sb, OX, OW2, aRow, bRow, acc);

        // ---- writeout: + b2 + rho[idx], straight from fragments ----
        #pragma unroll
        for (int mt = 0; mt < 2; mt++) {
            int rl = wm * 32 + mt * 16 + (lane >> 2);
            #pragma unroll
            for (int half = 0; half < 2; half++) {
                int row = rl + half * 8;
                long grow = base + row;
                if (grow < n) {
                    int seg = sIdx[row];
                    const float* rrow = &g_rho[(long)seg * D];
                    float* orow = &out[grow * D];
                    #pragma unroll
                    for (int nt = 0; nt < 4; nt++) {
                        int col = wn * 32 + nt * 8 + (lane & 3) * 2;
                        float* c = acc[mt][nt];
                        float2 g = *(const float2*)&rrow[col];
                        float2 o;
                        o.x = c[2 * half]     + sB2[col]     + g.x;
                        o.y = c[2 * half + 1] + sB2[col + 1] + g.y;
                        *(float2*)&orow[col] = o;
                    }
                }
            }
        }
    }
}

// ---------------- launch --------------------------------------------------------
extern "C" void kernel_launch(void* const* d_in, const int* in_sizes, int n_in,
                              void* d_out, int out_size) {
    const float* x      = (const float*)d_in[0];
    const int*   idx    = (const int*)  d_in[1];
    const float* phi_w1 = (const float*)d_in[2];
    const float* phi_b1 = (const float*)d_in[3];
    const float* phi_w2 = (const float*)d_in[4];
    const float* phi_b2 = (const float*)d_in[5];
    const float* rho_w1 = (const float*)d_in[6];
    const float* rho_b1 = (const float*)d_in[7];
    const float* rho_w2 = (const float*)d_in[8];
    const float* rho_b2 = (const float*)d_in[9];
    float* out = (float*)d_out;
    int n = in_sizes[1];

    size_t smem_rho = (size_t)(D * D + 2 * RSEG * D + D) * sizeof(float);
    cudaFuncSetAttribute(k_rho, cudaFuncAttributeMaxDynamicSharedMemorySize,
                         (int)smem_rho);
    cudaFuncSetAttribute(k_phi, cudaFuncAttributeMaxDynamicSharedMemorySize,
                         SMEM_PHI);

    k_zero<<<(NSEG * D / 4 + 255) / 256, 256>>>();

    int segsum_blocks = (n + CH - 1) / CH;
    k_segsum<<<segsum_blocks, 128>>>(x, idx, n);

    k_rho<<<NSEG / RSEG, 128, smem_rho>>>(rho_w1, rho_b1, rho_w2, rho_b2);

    k_phi<<<152, NTHR, SMEM_PHI>>>(x, idx, phi_w1, phi_b1, phi_w2, phi_b2,
                                   out, n);
}

// round 10
// speedup vs baseline: 2.1166x; 1.1012x over previous
#include <cuda_runtime.h>
#include <cuda_fp16.h>
#include <cstdint>

#define D     128
#define NSEG  4096
#define BM    128
#define NTHR  512
#define CH    1024
#define RSEG  32

#define WS    136            // padded fp16 row stride (272B)
#define WS2   (WS * 2)
#define XTILE (BM * WS2)     // 34816 B
#define WTILE (D * WS2)      // 34816 B
#define XFS   132            // f32 raw-stage row stride (floats)

// smem byte offsets
#define OX   0
#define OW1  (XTILE)
#define OW2  (XTILE + WTILE)
#define OXF  (XTILE + 2 * WTILE)                 // f32 raw X: 128*528 = 67584
#define OB1  (OXF + BM * XFS * 4)
#define OB2  (OB1 + 512)
#define OIDX0 (OB2 + 512)
#define OIDX1 (OIDX0 + 512)
#define SMEM_PHI (OIDX1 + 512)

// ---------------- scratch ----------------------------------------------------
__device__ float g_xsum[NSEG * D];
__device__ float g_rho [NSEG * D];

// ---------------- helpers ----------------------------------------------------
__device__ __forceinline__ uint32_t smem_u32(const void* p) {
    uint32_t a;
    asm("{ .reg .u64 t; cvta.to.shared.u64 t, %1; cvt.u32.u64 %0, t; }"
        : "=r"(a) : "l"(p));
    return a;
}
__device__ __forceinline__ void ldsm_x4(uint32_t r[4], uint32_t addr) {
    asm volatile("ldmatrix.sync.aligned.m8n8.x4.shared.b16 {%0,%1,%2,%3}, [%4];"
                 : "=r"(r[0]), "=r"(r[1]), "=r"(r[2]), "=r"(r[3]) : "r"(addr));
}
__device__ __forceinline__ void mma_f16(float c[4], const uint32_t a[4],
                                        const uint32_t* b) {
    asm volatile("mma.sync.aligned.m16n8k16.row.col.f32.f16.f16.f32 "
                 "{%0,%1,%2,%3}, {%4,%5,%6,%7}, {%8,%9}, {%0,%1,%2,%3};"
                 : "+f"(c[0]), "+f"(c[1]), "+f"(c[2]), "+f"(c[3])
                 : "r"(a[0]), "r"(a[1]), "r"(a[2]), "r"(a[3]),
                   "r"(b[0]), "r"(b[1]));
}
__device__ __forceinline__ uint32_t packh2(float a, float b) {
    __half2 h = __floats2half2_rn(a, b);
    return *(uint32_t*)&h;
}
__device__ __forceinline__ void cp16(uint32_t dst, const void* src) {
    asm volatile("cp.async.cg.shared.global [%0], [%1], 16;"
                 :: "r"(dst), "l"(src) : "memory");
}
#define CP_COMMIT() asm volatile("cp.async.commit_group;" ::: "memory")
#define CP_WAIT0()  asm volatile("cp.async.wait_group 0;" ::: "memory")

// ---------------- k0: zero ---------------------------------------------------
__global__ void k_zero() {
    int i = blockIdx.x * blockDim.x + threadIdx.x;
    if (i < NSEG * D / 4)
        reinterpret_cast<float4*>(g_xsum)[i] = make_float4(0.f, 0.f, 0.f, 0.f);
}

// ---------------- k1: segment sum, float4 lanes --------------------------------
__global__ void k_segsum(const float4* __restrict__ x4,
                         const int*    __restrict__ idx, int n) {
    int lane = threadIdx.x & 31;      // feature quad 0..31
    int rg   = threadIdx.x >> 5;      // row group 0..7
    long start = (long)blockIdx.x * CH;
    long end = start + CH; if (end > n) end = n;
    long nn = start + rg;
    if (nn >= end) return;

    int    cur = __ldg(&idx[nn]);
    float4 acc = make_float4(0.f, 0.f, 0.f, 0.f);

    for (; nn + 24 < end; nn += 32) {       // 4 steps of stride-8
        int s[4]; float4 v[4];
        #pragma unroll
        for (int u = 0; u < 4; u++) {
            s[u] = __ldg(&idx[nn + u * 8]);
            v[u] = __ldg(&x4[(nn + u * 8) * 32 + lane]);
        }
        #pragma unroll
        for (int u = 0; u < 4; u++) {
            if (s[u] != cur) {
                float* dst = &g_xsum[(long)cur * D + lane * 4];
                atomicAdd(dst,     acc.x); atomicAdd(dst + 1, acc.y);
                atomicAdd(dst + 2, acc.z); atomicAdd(dst + 3, acc.w);
                acc = make_float4(0.f, 0.f, 0.f, 0.f); cur = s[u];
            }
            acc.x += v[u].x; acc.y += v[u].y; acc.z += v[u].z; acc.w += v[u].w;
        }
    }
    for (; nn < end; nn += 8) {
        int s = __ldg(&idx[nn]);
        float4 v = __ldg(&x4[nn * 32 + lane]);
        if (s != cur) {
            float* dst = &g_xsum[(long)cur * D + lane * 4];
            atomicAdd(dst,     acc.x); atomicAdd(dst + 1, acc.y);
            atomicAdd(dst + 2, acc.z); atomicAdd(dst + 3, acc.w);
            acc = make_float4(0.f, 0.f, 0.f, 0.f); cur = s;
        }
        acc.x += v.x; acc.y += v.y; acc.z += v.z; acc.w += v.w;
    }
    float* dst = &g_xsum[(long)cur * D + lane * 4];
    atomicAdd(dst,     acc.x); atomicAdd(dst + 1, acc.y);
    atomicAdd(dst + 2, acc.z); atomicAdd(dst + 3, acc.w);
}

// ---------------- k2: rho MLP on segment sums ----------------------------------
__global__ void k_rho(const float* __restrict__ w1, const float* __restrict__ b1,
                      const float* __restrict__ w2, const float* __restrict__ b2) {
    extern __shared__ float sm[];
    float* sW = sm;
    float* sX = sW + D * D;
    float* sH = sX + RSEG * D;
    float* sB = sH + RSEG * D;
    int j = threadIdx.x;
    int seg0 = blockIdx.x * RSEG;

    for (int r = 0; r < RSEG; r++)
        sX[r * D + j] = g_xsum[(seg0 + r) * D + j];
    for (int i = j; i < D * D; i += blockDim.x) sW[i] = w1[i];
    sB[j] = b1[j];
    __syncthreads();

    for (int r = 0; r < RSEG; r++) {
        float acc = sB[j];
        #pragma unroll 8
        for (int k = 0; k < D; k++) acc += sX[r * D + k] * sW[k * D + j];
        sH[r * D + j] = fmaxf(acc, 0.f);
    }
    __syncthreads();
    for (int i = j; i < D * D; i += blockDim.x) sW[i] = w2[i];
    sB[j] = b2[j];
    __syncthreads();

    for (int r = 0; r < RSEG; r++) {
        float acc = sB[j];
        #pragma unroll 8
        for (int k = 0; k < D; k++) acc += sH[r * D + k] * sW[k * D + j];
        g_rho[(seg0 + r) * D + j] = acc;
    }
}

// ---------------- single-pass fp16 GEMM, warp tile 32x32 ------------------------
__device__ __forceinline__ void mma_layer(uint32_t sb, uint32_t aOff, uint32_t bOff,
                                          uint32_t aRow, uint32_t bRow,
                                          float acc[2][4][4]) {
    #pragma unroll
    for (int k = 0; k < 8; k++) {
        uint32_t a0[4], a1[4];
        ldsm_x4(a0, sb + aOff + aRow + k * 32);
        ldsm_x4(a1, sb + aOff + aRow + 16 * WS2 + k * 32);
        #pragma unroll
        for (int np = 0; np < 2; np++) {
            uint32_t b[4];
            ldsm_x4(b, sb + bOff + bRow + np * 16 * WS2 + k * 32);
            mma_f16(acc[0][2*np],   a0, b);
            mma_f16(acc[0][2*np+1], a0, b + 2);
            mma_f16(acc[1][2*np],   a1, b);
            mma_f16(acc[1][2*np+1], a1, b + 2);
        }
    }
}

// ---------------- k3: phi MLP (fp16, cp.async pipelined) ------------------------
__global__ __launch_bounds__(NTHR, 1)
void k_phi(const float* __restrict__ x, const int* __restrict__ idx,
           const float* __restrict__ w1, const float* __restrict__ b1,
           const float* __restrict__ w2, const float* __restrict__ b2,
           float* __restrict__ out, int n) {
    extern __shared__ char smem[];
    const uint32_t sb = smem_u32(smem);
    int tid = threadIdx.x, wid = tid >> 5, lane = tid & 31;
    int wm = wid >> 2, wn = wid & 3;      // 4 x 4 warp grid, warp tile 32x32

    // ---- prologue: weights -> W^T fp16, biases ----
    for (int i = tid; i < D * D; i += NTHR) {      // i = k*128 + j
        int k = i >> 7, j = i & 127;
        uint32_t o = (uint32_t)(j * WS + k) * 2;
        *(__half*)(smem + OW1 + o) = __float2half_rn(w1[i]);
        *(__half*)(smem + OW2 + o) = __float2half_rn(w2[i]);
    }
    if (tid < D) {
        ((float*)(smem + OB1))[tid] = b1[tid];
        ((float*)(smem + OB2))[tid] = b2[tid];
    }

    const float* sB1 = (const float*)(smem + OB1);
    const float* sB2 = (const float*)(smem + OB2);

    const uint32_t aRow = (uint32_t)(wm * 32 + (lane & 15)) * WS2
                        + (uint32_t)((lane >> 4) << 4);
    const uint32_t bRow = (uint32_t)(wn * 32 + (lane & 7) + ((lane >> 4) << 3)) * WS2
                        + (uint32_t)(((lane >> 3) & 1) << 4);

    const int ntiles = (n + BM - 1) / BM;

    // prefetch x rows + idx of tile t into OXF / OIDX{buf}
    auto prefetch = [&](int t, int buf) {
        long pb = (long)t * BM;
        #pragma unroll
        for (int it = 0; it < 8; ++it) {
            int c = it * NTHR + tid;          // chunk 0..4095
            int m = c >> 5, q = c & 31;
            if (pb + m < n)
                cp16(sb + OXF + (uint32_t)(m * XFS + q * 4) * 4,
                     x + (pb + m) * D + q * 4);
        }
        uint32_t oidx = buf ? (uint32_t)OIDX1 : (uint32_t)OIDX0;
        if (tid < 32 && pb + tid * 4 < n)     // 128 ints = 32 chunks
            cp16(sb + oidx + tid * 16, idx + pb + tid * 4);
        CP_COMMIT();
    };

    int tile = blockIdx.x;
    int cnt = 0;
    if (tile < ntiles) prefetch(tile, 0);

    for (; tile < ntiles; tile += gridDim.x, cnt ^= 1) {
        long base = (long)tile * BM;
        const int* sIdx = (const int*)(smem + (cnt ? OIDX1 : OIDX0));

        CP_WAIT0();
        __syncthreads();   // OXF/OIDX ready; previous tile fully consumed

        // ---- convert OXF (f32) -> OX (fp16) ----
        #pragma unroll
        for (int it = 0; it < 8; ++it) {
            int i = it * NTHR + tid;          // 0..4095 float4 slots
            int m = i >> 5, kq = i & 31;
            float4 v = make_float4(0.f, 0.f, 0.f, 0.f);
            if (base + m < n)
                v = *(const float4*)(smem + OXF + (uint32_t)(m * XFS + kq * 4) * 4);
            uint32_t o = (uint32_t)(m * WS + kq * 4) * 2;
            *(uint2*)(smem + OX + o) = make_uint2(packh2(v.x, v.y),
                                                  packh2(v.z, v.w));
        }
        __syncthreads();

        // ---- issue prefetch for next tile (idx -> other buffer) ----
        int nxt = tile + gridDim.x;
        if (nxt < ntiles) prefetch(nxt, cnt ^ 1);

        // ---- layer 1 ----
        float acc[2][4][4];
        #pragma unroll
        for (int a = 0; a < 2; a++)
            #pragma unroll
            for (int b = 0; b < 4; b++)
                #pragma unroll
                for (int c = 0; c < 4; c++) acc[a][b][c] = 0.f;
        mma_layer(sb, OX, OW1, aRow, bRow, acc);
        __syncthreads();   // all warps done reading X

        // ---- epilogue 1: relu(.+b1) -> fp16 back into X buffer ----
        #pragma unroll
        for (int mt = 0; mt < 2; mt++) {
            int r0 = wm * 32 + mt * 16 + (lane >> 2);
            #pragma unroll
            for (int nt = 0; nt < 4; nt++) {
                int col = wn * 32 + nt * 8 + (lane & 3) * 2;
                float* c = acc[mt][nt];
                float v0 = fmaxf(c[0] + sB1[col],     0.f);
                float v1 = fmaxf(c[1] + sB1[col + 1], 0.f);
                float v2 = fmaxf(c[2] + sB1[col],     0.f);
                float v3 = fmaxf(c[3] + sB1[col + 1], 0.f);
                *(uint32_t*)(smem + OX + (uint32_t)(r0 * WS + col) * 2)
                    = packh2(v0, v1);
                *(uint32_t*)(smem + OX + (uint32_t)((r0 + 8) * WS + col) * 2)
                    = packh2(v2, v3);
            }
        }
        __syncthreads();

        // ---- layer 2 ----
        #pragma unroll
        for (int a = 0; a < 2; a++)
            #pragma unroll
            for (int b = 0; b < 4; b++)
                #pragma unroll
                for (int c = 0; c < 4; c++) acc[a][b][c] = 0.f;
        mma_layer(sb, OX, OW2, aRow, bRow, acc);

        // ---- writeout: + b2 + rho[idx], streaming stores ----
        #pragma unroll
        for (int mt = 0; mt < 2; mt++) {
            int rl = wm * 32 + mt * 16 + (lane >> 2);
            #pragma unroll
            for (int half = 0; half < 2; half++) {
                int row = rl + half * 8;
                long grow = base + row;
                if (grow < n) {
                    int seg = sIdx[row];
                    const float* rrow = &g_rho[(long)seg * D];
                    float* orow = &out[grow * D];
                    #pragma unroll
                    for (int nt = 0; nt < 4; nt++) {
                        int col = wn * 32 + nt * 8 + (lane & 3) * 2;
                        float* c = acc[mt][nt];
                        float2 g = *(const float2*)&rrow[col];
                        float2 o;
                        o.x = c[2 * half]     + sB2[col]     + g.x;
                        o.y = c[2 * half + 1] + sB2[col + 1] + g.y;
                        __stcs((float2*)&orow[col], o);
                    }
                }
            }
        }
    }
}

// ---------------- launch --------------------------------------------------------
extern "C" void kernel_launch(void* const* d_in, const int* in_sizes, int n_in,
                              void* d_out, int out_size) {
    const float* x      = (const float*)d_in[0];
    const int*   idx    = (const int*)  d_in[1];
    const float* phi_w1 = (const float*)d_in[2];
    const float* phi_b1 = (const float*)d_in[3];
    const float* phi_w2 = (const float*)d_in[4];
    const float* phi_b2 = (const float*)d_in[5];
    const float* rho_w1 = (const float*)d_in[6];
    const float* rho_b1 = (const float*)d_in[7];
    const float* rho_w2 = (const float*)d_in[8];
    const float* rho_b2 = (const float*)d_in[9];
    float* out = (float*)d_out;
    int n = in_sizes[1];

    size_t smem_rho = (size_t)(D * D + 2 * RSEG * D + D) * sizeof(float);
    cudaFuncSetAttribute(k_rho, cudaFuncAttributeMaxDynamicSharedMemorySize,
                         (int)smem_rho);
    cudaFuncSetAttribute(k_phi, cudaFuncAttributeMaxDynamicSharedMemorySize,
                         SMEM_PHI);

    k_zero<<<(NSEG * D / 4 + 255) / 256, 256>>>();

    int segsum_blocks = (n + CH - 1) / CH;
    k_segsum<<<segsum_blocks, 256>>>((const float4*)x, idx, n);

    k_rho<<<NSEG / RSEG, 128, smem_rho>>>(rho_w1, rho_b1, rho_w2, rho_b2);

    k_phi<<<152, NTHR, SMEM_PHI>>>(x, idx, phi_w1, phi_b1, phi_w2, phi_b2,
                                   out, n);
}